// round 1
// baseline (speedup 1.0000x reference)
#include <cuda_runtime.h>
#include <cuda_bf16.h>

#define N_NODES   50000
#define N_EDGES   1600000
#define HID       128
#define N_LAYERS  3
#define N_GRAPHS  64
#define LN_EPS    1e-5f

// ---------------- static device scratch (no runtime alloc allowed) -------------
__device__ float g_agg [(size_t)N_NODES * HID];
__device__ float g_bufA[(size_t)N_NODES * HID];
__device__ float g_bufB[(size_t)N_NODES * HID];
__device__ float g_deg [N_NODES];           // becomes inv_deg after finalize
__device__ float g_gsum[N_GRAPHS * HID];
__device__ float g_gcnt[N_GRAPHS];

// ---------------- zeroing kernels ---------------------------------------------
__global__ void zero_misc_kernel() {
    int i = blockIdx.x * blockDim.x + threadIdx.x;
    if (i < N_NODES) g_deg[i] = 0.0f;
    if (i < N_GRAPHS * HID) g_gsum[i] = 0.0f;
    if (i < N_GRAPHS) g_gcnt[i] = 0.0f;
}

__global__ void zero_agg_kernel() {
    size_t i = (size_t)(blockIdx.x * blockDim.x + threadIdx.x) * 4;
    size_t total = (size_t)N_NODES * HID;
    if (i < total) *(float4*)(g_agg + i) = make_float4(0.f, 0.f, 0.f, 0.f);
}

// ---------------- degree ------------------------------------------------------
__global__ void deg_kernel(const int* __restrict__ ei, int nE) {
    int e = blockIdx.x * blockDim.x + threadIdx.x;
    if (e >= nE) return;
    int d = __ldg(ei + nE + e);
    atomicAdd(&g_deg[d], 1.0f);
}

__global__ void invdeg_kernel() {
    int i = blockIdx.x * blockDim.x + threadIdx.x;
    if (i < N_NODES) g_deg[i] = 1.0f / fmaxf(g_deg[i], 1.0f);
}

// ---------------- scatter: agg[dst] += x[src], warp per edge ------------------
__global__ __launch_bounds__(256) void scatter_kernel(
    const float* __restrict__ x, const int* __restrict__ ei, int nE)
{
    int w    = (blockIdx.x * blockDim.x + threadIdx.x) >> 5;
    int lane = threadIdx.x & 31;
    if (w >= nE) return;
    int s = __ldg(ei + w);
    int d = __ldg(ei + nE + w);
    float4 v = *(const float4*)(x + (size_t)s * HID + lane * 4);
    float* p = g_agg + (size_t)d * HID + lane * 4;
    asm volatile("red.global.add.v4.f32 [%0], {%1,%2,%3,%4};"
                 :: "l"(p), "f"(v.x), "f"(v.y), "f"(v.z), "f"(v.w) : "memory");
}

// ---------------- fused dual-GEMM + LayerNorm + ReLU --------------------------
// h = (agg * inv_deg) @ Wn + bn + x @ Wr ; LN(h)*gamma+beta ; relu -> xout
// block = 256 threads (16x16), tile = 64 rows x 128 cols.
#define TILE_R 64
#define APAD   132          // padded row stride (floats); 132*4B = 528B, 16B aligned

__global__ __launch_bounds__(256, 1) void fused_gemm_ln_kernel(
    const float* __restrict__ x_in,
    const float* __restrict__ Wn,  const float* __restrict__ bn,
    const float* __restrict__ Wr,  const float* __restrict__ gamma,
    const float* __restrict__ beta,
    float* __restrict__ x_out, int layer)
{
    extern __shared__ float sm[];
    float* Wn_s = sm;                         // 128*128
    float* Wr_s = sm + HID * HID;             // 128*128
    float* A_s  = Wr_s + HID * HID;           // 64*132
    float* X_s  = A_s + TILE_R * APAD;        // 64*132

    const int tid = threadIdx.x;
    const int tx  = tid & 15;                 // col group
    const int ty  = tid >> 4;                 // row group
    const int row0 = blockIdx.x * TILE_R;

    const float* Wn_l = Wn + (size_t)layer * HID * HID;
    const float* Wr_l = Wr + (size_t)layer * HID * HID;

    // stage weights: 16384 floats each, 256 threads -> 16 float4 per thread per matrix
    for (int idx = tid * 4; idx < HID * HID; idx += 256 * 4) {
        *(float4*)(Wn_s + idx) = *(const float4*)(Wn_l + idx);
        *(float4*)(Wr_s + idx) = *(const float4*)(Wr_l + idx);
    }

    // stage row tiles (agg scaled by inv_deg, x raw); 2048 float4 each
    for (int q = tid; q < TILE_R * (HID / 4); q += 256) {
        int r  = q >> 5;           // row in tile
        int c4 = q & 31;           // float4 index in row
        int row = row0 + r;
        float4 a = make_float4(0.f, 0.f, 0.f, 0.f);
        float4 xv = a;
        if (row < N_NODES) {
            float id = g_deg[row];   // inv_deg
            float4 t = *(const float4*)(g_agg + (size_t)row * HID + c4 * 4);
            a = make_float4(t.x * id, t.y * id, t.z * id, t.w * id);
            xv = *(const float4*)(x_in + (size_t)row * HID + c4 * 4);
        }
        *(float4*)(A_s + r * APAD + c4 * 4) = a;
        *(float4*)(X_s + r * APAD + c4 * 4) = xv;
    }
    __syncthreads();

    // accumulators: 4 rows x 8 cols; init with bias
    const int cbase = tx * 8;
    float acc[4][8];
    {
        float4 b0 = *(const float4*)(bn + layer * HID + cbase);
        float4 b1 = *(const float4*)(bn + layer * HID + cbase + 4);
        #pragma unroll
        for (int i = 0; i < 4; i++) {
            acc[i][0] = b0.x; acc[i][1] = b0.y; acc[i][2] = b0.z; acc[i][3] = b0.w;
            acc[i][4] = b1.x; acc[i][5] = b1.y; acc[i][6] = b1.z; acc[i][7] = b1.w;
        }
    }

    const int rb0 = ty * APAD, rb1 = (ty + 16) * APAD,
              rb2 = (ty + 32) * APAD, rb3 = (ty + 48) * APAD;

    #pragma unroll 2
    for (int k = 0; k < HID; k++) {
        float a0 = A_s[rb0 + k], a1 = A_s[rb1 + k], a2 = A_s[rb2 + k], a3 = A_s[rb3 + k];
        float x0 = X_s[rb0 + k], x1 = X_s[rb1 + k], x2 = X_s[rb2 + k], x3 = X_s[rb3 + k];
        float4 wn0 = *(float4*)(Wn_s + k * HID + cbase);
        float4 wn1 = *(float4*)(Wn_s + k * HID + cbase + 4);
        float4 wr0 = *(float4*)(Wr_s + k * HID + cbase);
        float4 wr1 = *(float4*)(Wr_s + k * HID + cbase + 4);
        float wn[8] = {wn0.x, wn0.y, wn0.z, wn0.w, wn1.x, wn1.y, wn1.z, wn1.w};
        float wr[8] = {wr0.x, wr0.y, wr0.z, wr0.w, wr1.x, wr1.y, wr1.z, wr1.w};
        #pragma unroll
        for (int j = 0; j < 8; j++) {
            acc[0][j] += a0 * wn[j] + x0 * wr[j];
            acc[1][j] += a1 * wn[j] + x1 * wr[j];
            acc[2][j] += a2 * wn[j] + x2 * wr[j];
            acc[3][j] += a3 * wn[j] + x3 * wr[j];
        }
    }

    // LayerNorm + affine + ReLU; row threads are a contiguous 16-lane half-warp
    float gm[8], bt[8];
    {
        float4 g0 = *(const float4*)(gamma + layer * HID + cbase);
        float4 g1 = *(const float4*)(gamma + layer * HID + cbase + 4);
        float4 b0 = *(const float4*)(beta  + layer * HID + cbase);
        float4 b1 = *(const float4*)(beta  + layer * HID + cbase + 4);
        gm[0]=g0.x; gm[1]=g0.y; gm[2]=g0.z; gm[3]=g0.w; gm[4]=g1.x; gm[5]=g1.y; gm[6]=g1.z; gm[7]=g1.w;
        bt[0]=b0.x; bt[1]=b0.y; bt[2]=b0.z; bt[3]=b0.w; bt[4]=b1.x; bt[5]=b1.y; bt[6]=b1.z; bt[7]=b1.w;
    }

    const float inv128 = 1.0f / 128.0f;
    #pragma unroll
    for (int i = 0; i < 4; i++) {
        float s = 0.f, q = 0.f;
        #pragma unroll
        for (int j = 0; j < 8; j++) { s += acc[i][j]; q += acc[i][j] * acc[i][j]; }
        #pragma unroll
        for (int m = 8; m >= 1; m >>= 1) {
            s += __shfl_xor_sync(0xffffffffu, s, m);
            q += __shfl_xor_sync(0xffffffffu, q, m);
        }
        float mu  = s * inv128;
        float var = q * inv128 - mu * mu;
        float rs  = rsqrtf(var + LN_EPS);
        int row = row0 + ty + 16 * i;
        if (row < N_NODES) {
            float o[8];
            #pragma unroll
            for (int j = 0; j < 8; j++) {
                float v = (acc[i][j] - mu) * rs * gm[j] + bt[j];
                o[j] = fmaxf(v, 0.0f);
            }
            *(float4*)(x_out + (size_t)row * HID + cbase)     = make_float4(o[0], o[1], o[2], o[3]);
            *(float4*)(x_out + (size_t)row * HID + cbase + 4) = make_float4(o[4], o[5], o[6], o[7]);
        }
    }
}

// ---------------- graph pooling (batch is sorted -> run-length partials) ------
__global__ __launch_bounds__(128) void pool_kernel(
    const float* __restrict__ node_emb, const int* __restrict__ batch)
{
    __shared__ int sb[128];
    int n0 = blockIdx.x * 128;
    int c  = threadIdx.x;
    int nmax = min(128, N_NODES - n0);
    if (c < nmax) sb[c] = batch[n0 + c];
    __syncthreads();

    float sum = 0.f;
    int curg = sb[0];
    int runlen = 0;
    for (int t = 0; t < nmax; t++) {
        int g = sb[t];
        if (g != curg) {
            atomicAdd(&g_gsum[curg * HID + c], sum);
            if (c == 0) atomicAdd(&g_gcnt[curg], (float)runlen);
            sum = 0.f; runlen = 0; curg = g;
        }
        sum += node_emb[(size_t)(n0 + t) * HID + c];
        runlen++;
    }
    atomicAdd(&g_gsum[curg * HID + c], sum);
    if (c == 0) atomicAdd(&g_gcnt[curg], (float)runlen);
}

__global__ void finalize_kernel(float* __restrict__ out_graph) {
    int g = blockIdx.x;
    int c = threadIdx.x;
    float cnt = fmaxf(g_gcnt[g], 1.0f);
    out_graph[g * HID + c] = g_gsum[g * HID + c] / cnt;
}

// ---------------- helper: fetch device pointers to the globals ----------------
__global__ void noop_kernel() {}

extern "C" void kernel_launch(void* const* d_in, const int* in_sizes, int n_in,
                              void* d_out, int out_size)
{
    const float* x     = (const float*)d_in[0];
    const float* Wn    = (const float*)d_in[1];
    const float* bn    = (const float*)d_in[2];
    const float* Wr    = (const float*)d_in[3];
    const float* gamma = (const float*)d_in[4];
    const float* beta  = (const float*)d_in[5];
    const int*   ei    = (const int*)  d_in[6];
    const int*   batch = (const int*)  d_in[7];
    float* out = (float*)d_out;
    float* out_graph = out;                         // [64,128]
    float* out_node  = out + N_GRAPHS * HID;        // [50000,128]

    const int nE = in_sizes[6] / 2;

    // device pointers to buffers (via symbol lookup; not a stream op)
    static float *pA = nullptr, *pB = nullptr;
    if (!pA) {
        cudaGetSymbolAddress((void**)&pA, g_bufA);
        cudaGetSymbolAddress((void**)&pB, g_bufB);
        size_t smem = (size_t)(2 * HID * HID + 2 * TILE_R * APAD) * sizeof(float);
        cudaFuncSetAttribute(fused_gemm_ln_kernel,
                             cudaFuncAttributeMaxDynamicSharedMemorySize, (int)smem);
    }
    size_t smem = (size_t)(2 * HID * HID + 2 * TILE_R * APAD) * sizeof(float);

    // zero deg / graph accumulators
    zero_misc_kernel<<<(N_NODES + 255) / 256, 256>>>();

    // degree + inverse degree
    deg_kernel<<<(nE + 255) / 256, 256>>>(ei, nE);
    invdeg_kernel<<<(N_NODES + 255) / 256, 256>>>();

    const int gemm_grid = (N_NODES + TILE_R - 1) / TILE_R;
    const int zero_grid = ((N_NODES * HID / 4) + 255) / 256;
    const int scat_grid = (nE * 32 + 255) / 256;

    const float* cur = x;
    float* nxt;
    for (int l = 0; l < N_LAYERS; l++) {
        nxt = (l == 0) ? pA : (l == 1) ? pB : out_node;
        zero_agg_kernel<<<zero_grid, 256>>>();
        scatter_kernel<<<scat_grid, 256>>>(cur, ei, nE);
        fused_gemm_ln_kernel<<<gemm_grid, 256, smem>>>(
            cur, Wn, bn, Wr, gamma, beta, nxt, l);
        cur = nxt;
    }

    // graph pooling
    pool_kernel<<<(N_NODES + 127) / 128, 128>>>(out_node, batch);
    finalize_kernel<<<N_GRAPHS, HID>>>(out_graph);
}

// round 4
// speedup vs baseline: 1.9714x; 1.9714x over previous
#include <cuda_runtime.h>
#include <cuda_bf16.h>

#define N_NODES   50000
#define N_EDGES   1600000
#define HID       128
#define N_LAYERS  3
#define N_GRAPHS  64
#define LN_EPS    1e-5f
#define SCAN_B    ((N_NODES + 255) / 256)   // 196

// ---------------- static device scratch ---------------------------------------
__device__ float g_agg [(size_t)N_NODES * HID];
__device__ float g_bufA[(size_t)N_NODES * HID];
__device__ float g_bufB[(size_t)N_NODES * HID];
__device__ int   g_deg_i[N_NODES];
__device__ int   g_cur  [N_NODES];
__device__ int   g_incl [N_NODES];
__device__ int   g_off  [N_NODES + 1];
__device__ int   g_part [256];
__device__ int   g_csr  [N_EDGES];
__device__ float g_gsum[N_GRAPHS * HID];
__device__ float g_gcnt[N_GRAPHS];

// ---------------- zero small buffers ------------------------------------------
__global__ void zero_small_kernel() {
    int i = blockIdx.x * blockDim.x + threadIdx.x;
    if (i < N_NODES) { g_deg_i[i] = 0; g_cur[i] = 0; }
    if (i < N_GRAPHS * HID) g_gsum[i] = 0.0f;
    if (i < N_GRAPHS) g_gcnt[i] = 0.0f;
}

// ---------------- CSR build ---------------------------------------------------
__global__ void count_kernel(const int* __restrict__ ei, int nE) {
    int e = blockIdx.x * blockDim.x + threadIdx.x;
    if (e >= nE) return;
    atomicAdd(&g_deg_i[__ldg(ei + nE + e)], 1);
}

__global__ void scan1_kernel() {
    __shared__ int s[256];
    int t = threadIdx.x;
    int i = blockIdx.x * 256 + t;
    int v = (i < N_NODES) ? g_deg_i[i] : 0;
    s[t] = v; __syncthreads();
    #pragma unroll
    for (int d = 1; d < 256; d <<= 1) {
        int u = (t >= d) ? s[t - d] : 0;
        __syncthreads();
        s[t] += u;
        __syncthreads();
    }
    if (i < N_NODES) g_incl[i] = s[t];
    if (t == 255) g_part[blockIdx.x] = s[255];
}

__global__ void scan2_kernel() {
    __shared__ int s[256];
    int t = threadIdx.x;
    int v = (t < SCAN_B) ? g_part[t] : 0;
    s[t] = v; __syncthreads();
    #pragma unroll
    for (int d = 1; d < 256; d <<= 1) {
        int u = (t >= d) ? s[t - d] : 0;
        __syncthreads();
        s[t] += u;
        __syncthreads();
    }
    g_part[t] = s[t] - v;   // exclusive
}

__global__ void scan3_kernel(int nE) {
    int i = blockIdx.x * blockDim.x + threadIdx.x;
    if (i < N_NODES) g_off[i] = g_part[i >> 8] + g_incl[i] - g_deg_i[i];
    if (i == 0) g_off[N_NODES] = nE;
}

__global__ void fill_kernel(const int* __restrict__ ei, int nE) {
    int e = blockIdx.x * blockDim.x + threadIdx.x;
    if (e >= nE) return;
    int s = __ldg(ei + e);
    int d = __ldg(ei + nE + e);
    int pos = g_off[d] + atomicAdd(&g_cur[d], 1);
    g_csr[pos] = s;
}

// ---------------- gather aggregation: warp per node ---------------------------
__global__ __launch_bounds__(256) void gather_kernel(const float* __restrict__ x)
{
    int w    = (blockIdx.x * blockDim.x + threadIdx.x) >> 5;
    int lane = threadIdx.x & 31;
    if (w >= N_NODES) return;
    int beg = g_off[w], end = g_off[w + 1];
    float4 acc = make_float4(0.f, 0.f, 0.f, 0.f);
    int j = beg;
    for (; j + 3 < end; j += 4) {
        int s0 = __ldg(&g_csr[j]);
        int s1 = __ldg(&g_csr[j + 1]);
        int s2 = __ldg(&g_csr[j + 2]);
        int s3 = __ldg(&g_csr[j + 3]);
        float4 v0 = *(const float4*)(x + (size_t)s0 * HID + lane * 4);
        float4 v1 = *(const float4*)(x + (size_t)s1 * HID + lane * 4);
        float4 v2 = *(const float4*)(x + (size_t)s2 * HID + lane * 4);
        float4 v3 = *(const float4*)(x + (size_t)s3 * HID + lane * 4);
        acc.x += v0.x + v1.x + v2.x + v3.x;
        acc.y += v0.y + v1.y + v2.y + v3.y;
        acc.z += v0.z + v1.z + v2.z + v3.z;
        acc.w += v0.w + v1.w + v2.w + v3.w;
    }
    for (; j < end; j++) {
        int s0 = __ldg(&g_csr[j]);
        float4 v0 = *(const float4*)(x + (size_t)s0 * HID + lane * 4);
        acc.x += v0.x; acc.y += v0.y; acc.z += v0.z; acc.w += v0.w;
    }
    float id = 1.0f / fmaxf((float)(end - beg), 1.0f);
    acc.x *= id; acc.y *= id; acc.z *= id; acc.w *= id;
    *(float4*)(g_agg + (size_t)w * HID + lane * 4) = acc;
}

// ---------------- fused dual-GEMM + LayerNorm + ReLU --------------------------
// tile: 128 rows x 128 cols, 256 threads, 8x8 micro-tile
// stage 1: agg @ Wn (+bn), stage 2: x @ Wr (same smem buffers), then LN+ReLU.
#define GT_ROWS 128

__device__ __forceinline__ void stage_tile(
    const float* __restrict__ src, float* __restrict__ A_s,
    const float* __restrict__ Wl, float* __restrict__ W_s,
    int row0, int tid)
{
    // weights: identity copy, 4096 float4 / 256 threads
    #pragma unroll
    for (int idx = tid * 4; idx < HID * HID; idx += 256 * 4)
        *(float4*)(W_s + idx) = *(const float4*)(Wl + idx);
    // A tile transposed to k-major: A_s[k*128 + r]
    for (int q = tid; q < GT_ROWS * (HID / 4); q += 256) {
        int r  = q & 127;       // lane-consecutive rows -> conflict-free STS
        int k4 = q >> 7;        // 0..31
        int row = row0 + r;
        float4 v = make_float4(0.f, 0.f, 0.f, 0.f);
        if (row < N_NODES) v = *(const float4*)(src + (size_t)row * HID + k4 * 4);
        int kb = k4 * 4;
        A_s[(kb + 0) * 128 + r] = v.x;
        A_s[(kb + 1) * 128 + r] = v.y;
        A_s[(kb + 2) * 128 + r] = v.z;
        A_s[(kb + 3) * 128 + r] = v.w;
    }
}

__global__ __launch_bounds__(256, 1) void fused_gemm_ln_kernel(
    const float* __restrict__ x_in,
    const float* __restrict__ Wn,  const float* __restrict__ bn,
    const float* __restrict__ Wr,  const float* __restrict__ gamma,
    const float* __restrict__ beta,
    float* __restrict__ x_out, int layer)
{
    extern __shared__ float sm[];
    float* W_s = sm;                 // [k][col], 128*128
    float* A_s = sm + HID * HID;     // [k][row], 128*128

    const int tid = threadIdx.x;
    const int tx  = tid & 15;        // col group: cols tx*4..+3 and 64+tx*4..+3
    const int ty  = tid >> 4;        // row group: rows ty*8..+7
    const int row0 = blockIdx.x * GT_ROWS;

    const float* Wn_l = Wn + (size_t)layer * HID * HID;
    const float* Wr_l = Wr + (size_t)layer * HID * HID;

    const int c0 = tx * 4;           // low col base
    const int c1 = 64 + tx * 4;      // high col base

    float acc[8][8];
    {
        float4 b0 = *(const float4*)(bn + layer * HID + c0);
        float4 b1 = *(const float4*)(bn + layer * HID + c1);
        #pragma unroll
        for (int i = 0; i < 8; i++) {
            acc[i][0] = b0.x; acc[i][1] = b0.y; acc[i][2] = b0.z; acc[i][3] = b0.w;
            acc[i][4] = b1.x; acc[i][5] = b1.y; acc[i][6] = b1.z; acc[i][7] = b1.w;
        }
    }

    const int arow = ty * 8;

    // ---- stage 1: agg @ Wn ----
    stage_tile(g_agg, A_s, Wn_l, W_s, row0, tid);
    __syncthreads();
    #pragma unroll 2
    for (int k = 0; k < HID; k++) {
        float4 a0 = *(float4*)(A_s + k * 128 + arow);
        float4 a1 = *(float4*)(A_s + k * 128 + arow + 4);
        float4 w0 = *(float4*)(W_s + k * HID + c0);
        float4 w1 = *(float4*)(W_s + k * HID + c1);
        float a[8] = {a0.x, a0.y, a0.z, a0.w, a1.x, a1.y, a1.z, a1.w};
        float w[8] = {w0.x, w0.y, w0.z, w0.w, w1.x, w1.y, w1.z, w1.w};
        #pragma unroll
        for (int i = 0; i < 8; i++)
            #pragma unroll
            for (int j = 0; j < 8; j++)
                acc[i][j] += a[i] * w[j];
    }
    __syncthreads();

    // ---- stage 2: x @ Wr ----
    stage_tile(x_in, A_s, Wr_l, W_s, row0, tid);
    __syncthreads();
    #pragma unroll 2
    for (int k = 0; k < HID; k++) {
        float4 a0 = *(float4*)(A_s + k * 128 + arow);
        float4 a1 = *(float4*)(A_s + k * 128 + arow + 4);
        float4 w0 = *(float4*)(W_s + k * HID + c0);
        float4 w1 = *(float4*)(W_s + k * HID + c1);
        float a[8] = {a0.x, a0.y, a0.z, a0.w, a1.x, a1.y, a1.z, a1.w};
        float w[8] = {w0.x, w0.y, w0.z, w0.w, w1.x, w1.y, w1.z, w1.w};
        #pragma unroll
        for (int i = 0; i < 8; i++)
            #pragma unroll
            for (int j = 0; j < 8; j++)
                acc[i][j] += a[i] * w[j];
    }

    // ---- LayerNorm + affine + ReLU ----
    float gm[8], bt[8];
    {
        float4 g0 = *(const float4*)(gamma + layer * HID + c0);
        float4 g1 = *(const float4*)(gamma + layer * HID + c1);
        float4 b0 = *(const float4*)(beta  + layer * HID + c0);
        float4 b1 = *(const float4*)(beta  + layer * HID + c1);
        gm[0]=g0.x; gm[1]=g0.y; gm[2]=g0.z; gm[3]=g0.w;
        gm[4]=g1.x; gm[5]=g1.y; gm[6]=g1.z; gm[7]=g1.w;
        bt[0]=b0.x; bt[1]=b0.y; bt[2]=b0.z; bt[3]=b0.w;
        bt[4]=b1.x; bt[5]=b1.y; bt[6]=b1.z; bt[7]=b1.w;
    }

    const float inv128 = 1.0f / 128.0f;
    #pragma unroll
    for (int i = 0; i < 8; i++) {
        float s = 0.f, q = 0.f;
        #pragma unroll
        for (int j = 0; j < 8; j++) { s += acc[i][j]; q += acc[i][j] * acc[i][j]; }
        #pragma unroll
        for (int m = 8; m >= 1; m >>= 1) {
            s += __shfl_xor_sync(0xffffffffu, s, m);
            q += __shfl_xor_sync(0xffffffffu, q, m);
        }
        float mu  = s * inv128;
        float var = q * inv128 - mu * mu;
        float rs  = rsqrtf(var + LN_EPS);
        int row = row0 + arow + i;
        if (row < N_NODES) {
            float o[8];
            #pragma unroll
            for (int j = 0; j < 8; j++)
                o[j] = fmaxf((acc[i][j] - mu) * rs * gm[j] + bt[j], 0.0f);
            *(float4*)(x_out + (size_t)row * HID + c0) = make_float4(o[0], o[1], o[2], o[3]);
            *(float4*)(x_out + (size_t)row * HID + c1) = make_float4(o[4], o[5], o[6], o[7]);
        }
    }
}

// ---------------- graph pooling (batch sorted -> run-length partials) ---------
__global__ __launch_bounds__(128) void pool_kernel(
    const float* __restrict__ node_emb, const int* __restrict__ batch)
{
    __shared__ int sb[128];
    int n0 = blockIdx.x * 128;
    int c  = threadIdx.x;
    int nmax = min(128, N_NODES - n0);
    if (c < nmax) sb[c] = batch[n0 + c];
    __syncthreads();

    float sum = 0.f;
    int curg = sb[0];
    int runlen = 0;
    for (int t = 0; t < nmax; t++) {
        int g = sb[t];
        if (g != curg) {
            atomicAdd(&g_gsum[curg * HID + c], sum);
            if (c == 0) atomicAdd(&g_gcnt[curg], (float)runlen);
            sum = 0.f; runlen = 0; curg = g;
        }
        sum += node_emb[(size_t)(n0 + t) * HID + c];
        runlen++;
    }
    atomicAdd(&g_gsum[curg * HID + c], sum);
    if (c == 0) atomicAdd(&g_gcnt[curg], (float)runlen);
}

__global__ void finalize_kernel(float* __restrict__ out_graph) {
    int g = blockIdx.x;
    int c = threadIdx.x;
    float cnt = fmaxf(g_gcnt[g], 1.0f);
    out_graph[g * HID + c] = g_gsum[g * HID + c] / cnt;
}

extern "C" void kernel_launch(void* const* d_in, const int* in_sizes, int n_in,
                              void* d_out, int out_size)
{
    const float* x     = (const float*)d_in[0];
    const float* Wn    = (const float*)d_in[1];
    const float* bn    = (const float*)d_in[2];
    const float* Wr    = (const float*)d_in[3];
    const float* gamma = (const float*)d_in[4];
    const float* beta  = (const float*)d_in[5];
    const int*   ei    = (const int*)  d_in[6];
    const int*   batch = (const int*)  d_in[7];
    float* out = (float*)d_out;
    float* out_graph = out;                       // [64,128]
    float* out_node  = out + N_GRAPHS * HID;      // [50000,128]

    const int nE = in_sizes[6] / 2;

    static float *pA = nullptr, *pB = nullptr;
    if (!pA) {
        cudaGetSymbolAddress((void**)&pA, g_bufA);
        cudaGetSymbolAddress((void**)&pB, g_bufB);
        cudaFuncSetAttribute(fused_gemm_ln_kernel,
                             cudaFuncAttributeMaxDynamicSharedMemorySize,
                             2 * HID * HID * (int)sizeof(float));
    }
    const size_t smem = 2 * HID * HID * sizeof(float);

    // CSR build
    zero_small_kernel<<<(N_NODES + 255) / 256, 256>>>();
    count_kernel<<<(nE + 255) / 256, 256>>>(ei, nE);
    scan1_kernel<<<SCAN_B, 256>>>();
    scan2_kernel<<<1, 256>>>();
    scan3_kernel<<<SCAN_B, 256>>>(nE);
    fill_kernel<<<(nE + 255) / 256, 256>>>(ei, nE);

    const int gemm_grid   = (N_NODES + GT_ROWS - 1) / GT_ROWS;
    const int gather_grid = (N_NODES * 32 + 255) / 256;

    const float* cur = x;
    float* nxt;
    for (int l = 0; l < N_LAYERS; l++) {
        nxt = (l == 0) ? pA : (l == 1) ? pB : out_node;
        gather_kernel<<<gather_grid, 256>>>(cur);
        fused_gemm_ln_kernel<<<gemm_grid, 256, smem>>>(
            cur, Wn, bn, Wr, gamma, beta, nxt, l);
        cur = nxt;
    }

    pool_kernel<<<(N_NODES + 127) / 128, 128>>>(out_node, batch);
    finalize_kernel<<<N_GRAPHS, HID>>>(out_graph);
}

// round 5
// speedup vs baseline: 2.1062x; 1.0684x over previous
#include <cuda_runtime.h>
#include <cuda_fp16.h>
#include <cuda_bf16.h>

#define N_NODES   50000
#define N_EDGES   1600000
#define HID       128
#define N_LAYERS  3
#define N_GRAPHS  64
#define LN_EPS    1e-5f
#define SCAN_B    ((N_NODES + 255) / 256)   // 196

// ---------------- static device scratch ---------------------------------------
__device__ float  g_agg [(size_t)N_NODES * HID];
__device__ float  g_bufA[(size_t)N_NODES * HID];
__device__ float  g_bufB[(size_t)N_NODES * HID];
__device__ __half g_xh  [(size_t)N_NODES * HID];   // fp16 shadow of layer input
__device__ int    g_deg_i[N_NODES];
__device__ int    g_cur  [N_NODES];
__device__ int    g_incl [N_NODES];
__device__ int    g_off  [N_NODES + 1];
__device__ int    g_part [256];
__device__ int    g_csr  [N_EDGES];
__device__ float  g_gsum[N_GRAPHS * HID];
__device__ float  g_gcnt[N_GRAPHS];

// ---------------- zero small buffers ------------------------------------------
__global__ void zero_small_kernel() {
    int i = blockIdx.x * blockDim.x + threadIdx.x;
    if (i < N_NODES) { g_deg_i[i] = 0; g_cur[i] = 0; }
    if (i < N_GRAPHS * HID) g_gsum[i] = 0.0f;
    if (i < N_GRAPHS) g_gcnt[i] = 0.0f;
}

// ---------------- CSR build ---------------------------------------------------
__global__ void count_kernel(const int* __restrict__ ei, int nE) {
    int e = blockIdx.x * blockDim.x + threadIdx.x;
    if (e >= nE) return;
    atomicAdd(&g_deg_i[__ldg(ei + nE + e)], 1);
}

__global__ void scan1_kernel() {
    __shared__ int s[256];
    int t = threadIdx.x;
    int i = blockIdx.x * 256 + t;
    int v = (i < N_NODES) ? g_deg_i[i] : 0;
    s[t] = v; __syncthreads();
    #pragma unroll
    for (int d = 1; d < 256; d <<= 1) {
        int u = (t >= d) ? s[t - d] : 0;
        __syncthreads();
        s[t] += u;
        __syncthreads();
    }
    if (i < N_NODES) g_incl[i] = s[t];
    if (t == 255) g_part[blockIdx.x] = s[255];
}

__global__ void scan2_kernel() {
    __shared__ int s[256];
    int t = threadIdx.x;
    int v = (t < SCAN_B) ? g_part[t] : 0;
    s[t] = v; __syncthreads();
    #pragma unroll
    for (int d = 1; d < 256; d <<= 1) {
        int u = (t >= d) ? s[t - d] : 0;
        __syncthreads();
        s[t] += u;
        __syncthreads();
    }
    g_part[t] = s[t] - v;   // exclusive
}

__global__ void scan3_kernel(int nE) {
    int i = blockIdx.x * blockDim.x + threadIdx.x;
    if (i < N_NODES) g_off[i] = g_part[i >> 8] + g_incl[i] - g_deg_i[i];
    if (i == 0) g_off[N_NODES] = nE;
}

__global__ void fill_kernel(const int* __restrict__ ei, int nE) {
    int e = blockIdx.x * blockDim.x + threadIdx.x;
    if (e >= nE) return;
    int s = __ldg(ei + e);
    int d = __ldg(ei + nE + e);
    int pos = g_off[d] + atomicAdd(&g_cur[d], 1);
    g_csr[pos] = s;
}

// ---------------- fp32 -> fp16 shadow convert (layer 0 input) -----------------
__global__ void convert_half_kernel(const float* __restrict__ x) {
    size_t i = (size_t)(blockIdx.x * blockDim.x + threadIdx.x) * 4;
    if (i >= (size_t)N_NODES * HID) return;
    float4 v = *(const float4*)(x + i);
    __half2 h0 = __floats2half2_rn(v.x, v.y);
    __half2 h1 = __floats2half2_rn(v.z, v.w);
    uint2 packed;
    packed.x = *(unsigned*)&h0;
    packed.y = *(unsigned*)&h1;
    *(uint2*)(g_xh + i) = packed;
}

// ---------------- gather aggregation from fp16 table: warp per node -----------
__global__ __launch_bounds__(256) void gather_kernel()
{
    int w    = (blockIdx.x * blockDim.x + threadIdx.x) >> 5;
    int lane = threadIdx.x & 31;
    if (w >= N_NODES) return;
    int beg = g_off[w], end = g_off[w + 1];
    float a0 = 0.f, a1 = 0.f, a2 = 0.f, a3 = 0.f;
    int j = beg;
    for (; j + 3 < end; j += 4) {
        int s0 = __ldg(&g_csr[j]);
        int s1 = __ldg(&g_csr[j + 1]);
        int s2 = __ldg(&g_csr[j + 2]);
        int s3 = __ldg(&g_csr[j + 3]);
        uint2 v0 = __ldg((const uint2*)(g_xh + (size_t)s0 * HID) + lane);
        uint2 v1 = __ldg((const uint2*)(g_xh + (size_t)s1 * HID) + lane);
        uint2 v2 = __ldg((const uint2*)(g_xh + (size_t)s2 * HID) + lane);
        uint2 v3 = __ldg((const uint2*)(g_xh + (size_t)s3 * HID) + lane);
        float2 f;
        f = __half22float2(*(__half2*)&v0.x); a0 += f.x; a1 += f.y;
        f = __half22float2(*(__half2*)&v0.y); a2 += f.x; a3 += f.y;
        f = __half22float2(*(__half2*)&v1.x); a0 += f.x; a1 += f.y;
        f = __half22float2(*(__half2*)&v1.y); a2 += f.x; a3 += f.y;
        f = __half22float2(*(__half2*)&v2.x); a0 += f.x; a1 += f.y;
        f = __half22float2(*(__half2*)&v2.y); a2 += f.x; a3 += f.y;
        f = __half22float2(*(__half2*)&v3.x); a0 += f.x; a1 += f.y;
        f = __half22float2(*(__half2*)&v3.y); a2 += f.x; a3 += f.y;
    }
    for (; j < end; j++) {
        int s0 = __ldg(&g_csr[j]);
        uint2 v0 = __ldg((const uint2*)(g_xh + (size_t)s0 * HID) + lane);
        float2 f;
        f = __half22float2(*(__half2*)&v0.x); a0 += f.x; a1 += f.y;
        f = __half22float2(*(__half2*)&v0.y); a2 += f.x; a3 += f.y;
    }
    float id = 1.0f / fmaxf((float)(end - beg), 1.0f);
    *(float4*)(g_agg + (size_t)w * HID + lane * 4) =
        make_float4(a0 * id, a1 * id, a2 * id, a3 * id);
}

// ---------------- fused dual-GEMM + LayerNorm + ReLU --------------------------
// tile: 128 rows x 128 cols, 256 threads, 8x8 micro-tile
// stage 1: agg @ Wn (+bn), stage 2: x @ Wr (same smem buffers), then LN+ReLU.
#define GT_ROWS 128

__device__ __forceinline__ void stage_tile(
    const float* __restrict__ src, float* __restrict__ A_s,
    const float* __restrict__ Wl, float* __restrict__ W_s,
    int row0, int tid)
{
    #pragma unroll
    for (int idx = tid * 4; idx < HID * HID; idx += 256 * 4)
        *(float4*)(W_s + idx) = *(const float4*)(Wl + idx);
    for (int q = tid; q < GT_ROWS * (HID / 4); q += 256) {
        int r  = q & 127;
        int k4 = q >> 7;
        int row = row0 + r;
        float4 v = make_float4(0.f, 0.f, 0.f, 0.f);
        if (row < N_NODES) v = *(const float4*)(src + (size_t)row * HID + k4 * 4);
        int kb = k4 * 4;
        A_s[(kb + 0) * 128 + r] = v.x;
        A_s[(kb + 1) * 128 + r] = v.y;
        A_s[(kb + 2) * 128 + r] = v.z;
        A_s[(kb + 3) * 128 + r] = v.w;
    }
}

__global__ __launch_bounds__(256, 1) void fused_gemm_ln_kernel(
    const float* __restrict__ x_in,
    const float* __restrict__ Wn,  const float* __restrict__ bn,
    const float* __restrict__ Wr,  const float* __restrict__ gamma,
    const float* __restrict__ beta,
    float* __restrict__ x_out, int layer, int write_half)
{
    extern __shared__ float sm[];
    float* W_s = sm;
    float* A_s = sm + HID * HID;

    const int tid = threadIdx.x;
    const int tx  = tid & 15;
    const int ty  = tid >> 4;
    const int row0 = blockIdx.x * GT_ROWS;

    const float* Wn_l = Wn + (size_t)layer * HID * HID;
    const float* Wr_l = Wr + (size_t)layer * HID * HID;

    const int c0 = tx * 4;
    const int c1 = 64 + tx * 4;

    float acc[8][8];
    {
        float4 b0 = *(const float4*)(bn + layer * HID + c0);
        float4 b1 = *(const float4*)(bn + layer * HID + c1);
        #pragma unroll
        for (int i = 0; i < 8; i++) {
            acc[i][0] = b0.x; acc[i][1] = b0.y; acc[i][2] = b0.z; acc[i][3] = b0.w;
            acc[i][4] = b1.x; acc[i][5] = b1.y; acc[i][6] = b1.z; acc[i][7] = b1.w;
        }
    }

    const int arow = ty * 8;

    // ---- stage 1: agg @ Wn ----
    stage_tile(g_agg, A_s, Wn_l, W_s, row0, tid);
    __syncthreads();
    #pragma unroll 2
    for (int k = 0; k < HID; k++) {
        float4 a0 = *(float4*)(A_s + k * 128 + arow);
        float4 a1 = *(float4*)(A_s + k * 128 + arow + 4);
        float4 w0 = *(float4*)(W_s + k * HID + c0);
        float4 w1 = *(float4*)(W_s + k * HID + c1);
        float a[8] = {a0.x, a0.y, a0.z, a0.w, a1.x, a1.y, a1.z, a1.w};
        float w[8] = {w0.x, w0.y, w0.z, w0.w, w1.x, w1.y, w1.z, w1.w};
        #pragma unroll
        for (int i = 0; i < 8; i++)
            #pragma unroll
            for (int j = 0; j < 8; j++)
                acc[i][j] += a[i] * w[j];
    }
    __syncthreads();

    // ---- stage 2: x @ Wr ----
    stage_tile(x_in, A_s, Wr_l, W_s, row0, tid);
    __syncthreads();
    #pragma unroll 2
    for (int k = 0; k < HID; k++) {
        float4 a0 = *(float4*)(A_s + k * 128 + arow);
        float4 a1 = *(float4*)(A_s + k * 128 + arow + 4);
        float4 w0 = *(float4*)(W_s + k * HID + c0);
        float4 w1 = *(float4*)(W_s + k * HID + c1);
        float a[8] = {a0.x, a0.y, a0.z, a0.w, a1.x, a1.y, a1.z, a1.w};
        float w[8] = {w0.x, w0.y, w0.z, w0.w, w1.x, w1.y, w1.z, w1.w};
        #pragma unroll
        for (int i = 0; i < 8; i++)
            #pragma unroll
            for (int j = 0; j < 8; j++)
                acc[i][j] += a[i] * w[j];
    }

    // ---- LayerNorm + affine + ReLU ----
    float gm[8], bt[8];
    {
        float4 g0 = *(const float4*)(gamma + layer * HID + c0);
        float4 g1 = *(const float4*)(gamma + layer * HID + c1);
        float4 b0 = *(const float4*)(beta  + layer * HID + c0);
        float4 b1 = *(const float4*)(beta  + layer * HID + c1);
        gm[0]=g0.x; gm[1]=g0.y; gm[2]=g0.z; gm[3]=g0.w;
        gm[4]=g1.x; gm[5]=g1.y; gm[6]=g1.z; gm[7]=g1.w;
        bt[0]=b0.x; bt[1]=b0.y; bt[2]=b0.z; bt[3]=b0.w;
        bt[4]=b1.x; bt[5]=b1.y; bt[6]=b1.z; bt[7]=b1.w;
    }

    const float inv128 = 1.0f / 128.0f;
    #pragma unroll
    for (int i = 0; i < 8; i++) {
        float s = 0.f, q = 0.f;
        #pragma unroll
        for (int j = 0; j < 8; j++) { s += acc[i][j]; q += acc[i][j] * acc[i][j]; }
        #pragma unroll
        for (int m = 8; m >= 1; m >>= 1) {
            s += __shfl_xor_sync(0xffffffffu, s, m);
            q += __shfl_xor_sync(0xffffffffu, q, m);
        }
        float mu  = s * inv128;
        float var = q * inv128 - mu * mu;
        float rs  = rsqrtf(var + LN_EPS);
        int row = row0 + arow + i;
        if (row < N_NODES) {
            float o[8];
            #pragma unroll
            for (int j = 0; j < 8; j++)
                o[j] = fmaxf((acc[i][j] - mu) * rs * gm[j] + bt[j], 0.0f);
            *(float4*)(x_out + (size_t)row * HID + c0) = make_float4(o[0], o[1], o[2], o[3]);
            *(float4*)(x_out + (size_t)row * HID + c1) = make_float4(o[4], o[5], o[6], o[7]);
            if (write_half) {
                __half2 h0 = __floats2half2_rn(o[0], o[1]);
                __half2 h1 = __floats2half2_rn(o[2], o[3]);
                __half2 h2 = __floats2half2_rn(o[4], o[5]);
                __half2 h3 = __floats2half2_rn(o[6], o[7]);
                uint2 p0; p0.x = *(unsigned*)&h0; p0.y = *(unsigned*)&h1;
                uint2 p1; p1.x = *(unsigned*)&h2; p1.y = *(unsigned*)&h3;
                *(uint2*)(g_xh + (size_t)row * HID + c0) = p0;
                *(uint2*)(g_xh + (size_t)row * HID + c1) = p1;
            }
        }
    }
}

// ---------------- graph pooling (batch sorted -> run-length partials) ---------
__global__ __launch_bounds__(128) void pool_kernel(
    const float* __restrict__ node_emb, const int* __restrict__ batch)
{
    __shared__ int sb[128];
    int n0 = blockIdx.x * 128;
    int c  = threadIdx.x;
    int nmax = min(128, N_NODES - n0);
    if (c < nmax) sb[c] = batch[n0 + c];
    __syncthreads();

    float sum = 0.f;
    int curg = sb[0];
    int runlen = 0;
    for (int t = 0; t < nmax; t++) {
        int g = sb[t];
        if (g != curg) {
            atomicAdd(&g_gsum[curg * HID + c], sum);
            if (c == 0) atomicAdd(&g_gcnt[curg], (float)runlen);
            sum = 0.f; runlen = 0; curg = g;
        }
        sum += node_emb[(size_t)(n0 + t) * HID + c];
        runlen++;
    }
    atomicAdd(&g_gsum[curg * HID + c], sum);
    if (c == 0) atomicAdd(&g_gcnt[curg], (float)runlen);
}

__global__ void finalize_kernel(float* __restrict__ out_graph) {
    int g = blockIdx.x;
    int c = threadIdx.x;
    float cnt = fmaxf(g_gcnt[g], 1.0f);
    out_graph[g * HID + c] = g_gsum[g * HID + c] / cnt;
}

extern "C" void kernel_launch(void* const* d_in, const int* in_sizes, int n_in,
                              void* d_out, int out_size)
{
    const float* x     = (const float*)d_in[0];
    const float* Wn    = (const float*)d_in[1];
    const float* bn    = (const float*)d_in[2];
    const float* Wr    = (const float*)d_in[3];
    const float* gamma = (const float*)d_in[4];
    const float* beta  = (const float*)d_in[5];
    const int*   ei    = (const int*)  d_in[6];
    const int*   batch = (const int*)  d_in[7];
    float* out = (float*)d_out;
    float* out_graph = out;                       // [64,128]
    float* out_node  = out + N_GRAPHS * HID;      // [50000,128]

    const int nE = in_sizes[6] / 2;

    static float *pA = nullptr, *pB = nullptr;
    if (!pA) {
        cudaGetSymbolAddress((void**)&pA, g_bufA);
        cudaGetSymbolAddress((void**)&pB, g_bufB);
        cudaFuncSetAttribute(fused_gemm_ln_kernel,
                             cudaFuncAttributeMaxDynamicSharedMemorySize,
                             2 * HID * HID * (int)sizeof(float));
    }
    const size_t smem = 2 * HID * HID * sizeof(float);

    // CSR build
    zero_small_kernel<<<(N_NODES + 255) / 256, 256>>>();
    count_kernel<<<(nE + 255) / 256, 256>>>(ei, nE);
    scan1_kernel<<<SCAN_B, 256>>>();
    scan2_kernel<<<1, 256>>>();
    scan3_kernel<<<SCAN_B, 256>>>(nE);
    fill_kernel<<<(nE + 255) / 256, 256>>>(ei, nE);

    // fp16 shadow of layer-0 input
    convert_half_kernel<<<((N_NODES * HID / 4) + 255) / 256, 256>>>(x);

    const int gemm_grid   = (N_NODES + GT_ROWS - 1) / GT_ROWS;
    const int gather_grid = (N_NODES * 32 + 255) / 256;

    const float* cur = x;
    float* nxt;
    for (int l = 0; l < N_LAYERS; l++) {
        nxt = (l == 0) ? pA : (l == 1) ? pB : out_node;
        gather_kernel<<<gather_grid, 256>>>();
        fused_gemm_ln_kernel<<<gemm_grid, 256, smem>>>(
            cur, Wn, bn, Wr, gamma, beta, nxt, l, (l < N_LAYERS - 1) ? 1 : 0);
        cur = nxt;
    }

    pool_kernel<<<(N_NODES + 127) / 128, 128>>>(out_node, batch);
    finalize_kernel<<<N_GRAPHS, HID>>>(out_graph);
}

// round 7
// speedup vs baseline: 3.6974x; 1.7555x over previous
#include <cuda_runtime.h>
#include <cuda_fp16.h>
#include <cuda_bf16.h>

#define N_NODES   50000
#define N_EDGES   1600000
#define HID       128
#define KTOT      256            // combined K = [agg | x]
#define N_LAYERS  3
#define N_GRAPHS  64
#define LN_EPS    1e-5f
#define SCAN_B    ((N_NODES + 255) / 256)   // 196

// ---------------- static device scratch ---------------------------------------
__device__ __half g_xh  [(size_t)N_NODES * HID];    // fp16 layer input
__device__ __half g_aggh[(size_t)N_NODES * HID];    // fp16 mean-aggregated neighbors
__device__ __half g_wh  [(size_t)N_LAYERS * HID * KTOT]; // [l][n][k] (k<128:Wn, k>=128:Wr), transposed
__device__ int    g_deg_i[N_NODES];
__device__ int    g_cur  [N_NODES];
__device__ int    g_incl [N_NODES];
__device__ int    g_off  [N_NODES + 1];
__device__ int    g_part [256];
__device__ int    g_csr  [N_EDGES];
__device__ float  g_gsum[N_GRAPHS * HID];
__device__ float  g_gcnt[N_GRAPHS];

// ---------------- zero small buffers ------------------------------------------
__global__ void zero_small_kernel() {
    int i = blockIdx.x * blockDim.x + threadIdx.x;
    if (i < N_NODES) { g_deg_i[i] = 0; g_cur[i] = 0; }
    if (i < N_GRAPHS * HID) g_gsum[i] = 0.0f;
    if (i < N_GRAPHS) g_gcnt[i] = 0.0f;
}

// ---------------- CSR build ---------------------------------------------------
__global__ void count_kernel(const int* __restrict__ ei, int nE) {
    int e = blockIdx.x * blockDim.x + threadIdx.x;
    if (e >= nE) return;
    atomicAdd(&g_deg_i[__ldg(ei + nE + e)], 1);
}

__global__ void scan1_kernel() {
    __shared__ int s[256];
    int t = threadIdx.x;
    int i = blockIdx.x * 256 + t;
    int v = (i < N_NODES) ? g_deg_i[i] : 0;
    s[t] = v; __syncthreads();
    #pragma unroll
    for (int d = 1; d < 256; d <<= 1) {
        int u = (t >= d) ? s[t - d] : 0;
        __syncthreads();
        s[t] += u;
        __syncthreads();
    }
    if (i < N_NODES) g_incl[i] = s[t];
    if (t == 255) g_part[blockIdx.x] = s[255];
}

__global__ void scan2_kernel() {
    __shared__ int s[256];
    int t = threadIdx.x;
    int v = (t < SCAN_B) ? g_part[t] : 0;
    s[t] = v; __syncthreads();
    #pragma unroll
    for (int d = 1; d < 256; d <<= 1) {
        int u = (t >= d) ? s[t - d] : 0;
        __syncthreads();
        s[t] += u;
        __syncthreads();
    }
    g_part[t] = s[t] - v;   // exclusive
}

__global__ void scan3_kernel(int nE) {
    int i = blockIdx.x * blockDim.x + threadIdx.x;
    if (i < N_NODES) g_off[i] = g_part[i >> 8] + g_incl[i] - g_deg_i[i];
    if (i == 0) g_off[N_NODES] = nE;
}

__global__ void fill_kernel(const int* __restrict__ ei, int nE) {
    int e = blockIdx.x * blockDim.x + threadIdx.x;
    if (e >= nE) return;
    int s = __ldg(ei + e);
    int d = __ldg(ei + nE + e);
    int pos = g_off[d] + atomicAdd(&g_cur[d], 1);
    g_csr[pos] = s;
}

// ---------------- fp32 -> fp16 input convert ----------------------------------
__global__ void convert_half_kernel(const float* __restrict__ x) {
    size_t i = (size_t)(blockIdx.x * blockDim.x + threadIdx.x) * 4;
    if (i >= (size_t)N_NODES * HID) return;
    float4 v = *(const float4*)(x + i);
    __half2 h0 = __floats2half2_rn(v.x, v.y);
    __half2 h1 = __floats2half2_rn(v.z, v.w);
    uint2 packed;
    packed.x = *(unsigned*)&h0;
    packed.y = *(unsigned*)&h1;
    *(uint2*)(g_xh + i) = packed;
}

// ---------------- weight transpose + fp16 convert: g_wh[l][n][k] --------------
__global__ void wtrans_kernel(const float* __restrict__ Wn, const float* __restrict__ Wr) {
    int idx = blockIdx.x * 256 + threadIdx.x;     // l*32768 + n*256 + k
    if (idx >= N_LAYERS * HID * KTOT) return;
    int k = idx & 255;
    int n = (idx >> 8) & 127;
    int l = idx >> 15;
    float v = (k < HID) ? __ldg(&Wn[((size_t)l * HID + k) * HID + n])
                        : __ldg(&Wr[((size_t)l * HID + (k - HID)) * HID + n]);
    g_wh[idx] = __float2half_rn(v);
}

// ---------------- gather aggregation from fp16 table: warp per node -----------
__global__ __launch_bounds__(256) void gather_kernel()
{
    int w    = (blockIdx.x * blockDim.x + threadIdx.x) >> 5;
    int lane = threadIdx.x & 31;
    if (w >= N_NODES) return;
    int beg = g_off[w], end = g_off[w + 1];
    float a0 = 0.f, a1 = 0.f, a2 = 0.f, a3 = 0.f;
    int j = beg;
    for (; j + 3 < end; j += 4) {
        int s0 = __ldg(&g_csr[j]);
        int s1 = __ldg(&g_csr[j + 1]);
        int s2 = __ldg(&g_csr[j + 2]);
        int s3 = __ldg(&g_csr[j + 3]);
        uint2 v0 = __ldg((const uint2*)(g_xh + (size_t)s0 * HID) + lane);
        uint2 v1 = __ldg((const uint2*)(g_xh + (size_t)s1 * HID) + lane);
        uint2 v2 = __ldg((const uint2*)(g_xh + (size_t)s2 * HID) + lane);
        uint2 v3 = __ldg((const uint2*)(g_xh + (size_t)s3 * HID) + lane);
        float2 f;
        f = __half22float2(*(__half2*)&v0.x); a0 += f.x; a1 += f.y;
        f = __half22float2(*(__half2*)&v0.y); a2 += f.x; a3 += f.y;
        f = __half22float2(*(__half2*)&v1.x); a0 += f.x; a1 += f.y;
        f = __half22float2(*(__half2*)&v1.y); a2 += f.x; a3 += f.y;
        f = __half22float2(*(__half2*)&v2.x); a0 += f.x; a1 += f.y;
        f = __half22float2(*(__half2*)&v2.y); a2 += f.x; a3 += f.y;
        f = __half22float2(*(__half2*)&v3.x); a0 += f.x; a1 += f.y;
        f = __half22float2(*(__half2*)&v3.y); a2 += f.x; a3 += f.y;
    }
    for (; j < end; j++) {
        int s0 = __ldg(&g_csr[j]);
        uint2 v0 = __ldg((const uint2*)(g_xh + (size_t)s0 * HID) + lane);
        float2 f;
        f = __half22float2(*(__half2*)&v0.x); a0 += f.x; a1 += f.y;
        f = __half22float2(*(__half2*)&v0.y); a2 += f.x; a3 += f.y;
    }
    float id = 1.0f / fmaxf((float)(end - beg), 1.0f);
    __half2 h0 = __floats2half2_rn(a0 * id, a1 * id);
    __half2 h1 = __floats2half2_rn(a2 * id, a3 * id);
    uint2 packed;
    packed.x = *(unsigned*)&h0;
    packed.y = *(unsigned*)&h1;
    ((uint2*)(g_aggh + (size_t)w * HID))[lane] = packed;
}

// ---------------- HMMA fused dual-GEMM + LN + ReLU ----------------------------
// h[128x128] = [aggh | xh][128x256] @ g_wh^T ; bias; LN; ReLU
// block = 256 thr (8 warps: 4 along m x 2 along n), warp tile 32m x 64n.
// smem: A [128][256] half swizzled + W [128 n][256 k] half swizzled = 128 KB.
#define GT_ROWS 128

__device__ __forceinline__ unsigned ldsm_addr(const __half* base_sm, int row, int chunk) {
    // element addr in halves: (row*32 + (chunk ^ (row&7))) * 8
    return (unsigned)__cvta_generic_to_shared(base_sm) +
           (((row << 5) + (chunk ^ (row & 7))) << 4);
}

__global__ __launch_bounds__(256, 1) void hmma_ln_kernel(
    const float* __restrict__ bn, const float* __restrict__ gamma,
    const float* __restrict__ beta, float* __restrict__ out_fp32,
    int layer, int write_fp32)
{
    extern __shared__ __half smh[];
    __half* A_s = smh;                  // 128*256
    __half* W_s = smh + GT_ROWS * KTOT; // 128*256
    float*  red = (float*)smh;          // epilogue reuse: red_s[256], red_q[256]

    const int tid  = threadIdx.x;
    const int lane = tid & 31;
    const int warp = tid >> 5;
    const int wm   = warp & 3;          // m group
    const int wn   = warp >> 2;         // n group
    const int m0   = wm * 32;
    const int n0   = wn * 64;
    const int row0 = blockIdx.x * GT_ROWS;

    // ---- stage A: rows of [aggh | xh]; 32 chunks of 16B per row ----
    for (int q = tid; q < GT_ROWS * 32; q += 256) {
        int r = q >> 5;
        int c = q & 31;
        int row = row0 + r;
        uint4 v = make_uint4(0, 0, 0, 0);
        if (row < N_NODES) {
            const __half* src = (c < 16) ? (g_aggh + (size_t)row * HID + c * 8)
                                         : (g_xh  + (size_t)row * HID + (c - 16) * 8);
            v = *(const uint4*)src;
        }
        *(uint4*)(A_s + (((r << 5) + (c ^ (r & 7))) << 3)) = v;
    }
    // ---- stage W: g_wh[layer][n][k] ----
    const __half* wl = g_wh + (size_t)layer * HID * KTOT;
    for (int q = tid; q < HID * 32; q += 256) {
        int n = q >> 5;
        int c = q & 31;
        uint4 v = *(const uint4*)(wl + (size_t)n * KTOT + c * 8);
        *(uint4*)(W_s + (((n << 5) + (c ^ (n & 7))) << 3)) = v;
    }
    __syncthreads();

    // ---- MMA mainloop ----
    float acc[2][8][4];
    #pragma unroll
    for (int mt = 0; mt < 2; mt++)
        #pragma unroll
        for (int nt = 0; nt < 8; nt++)
            #pragma unroll
            for (int v = 0; v < 4; v++) acc[mt][nt][v] = 0.0f;

    // per-lane ldmatrix row indices
    const int a_row0 = m0 + (lane & 15);           // + mt*16
    const int b_row0 = n0 + (lane & 15);           // + g*16
    const int hi     = lane >> 4;                  // chunk offset within k-step

    #pragma unroll 4
    for (int kk = 0; kk < KTOT / 16; kk++) {
        int cbase = kk * 2 + hi;
        // A fragments: 2 m-tiles
        unsigned a[2][4];
        #pragma unroll
        for (int mt = 0; mt < 2; mt++) {
            unsigned addr = ldsm_addr(A_s, a_row0 + mt * 16, cbase);
            asm volatile("ldmatrix.sync.aligned.m8n8.x4.shared.b16 {%0,%1,%2,%3}, [%4];"
                         : "=r"(a[mt][0]), "=r"(a[mt][1]), "=r"(a[mt][2]), "=r"(a[mt][3])
                         : "r"(addr));
        }
        // B fragments: 4 x4-loads, each covers 2 n-tiles (n16 x k16)
        unsigned b[8][2];
        #pragma unroll
        for (int g = 0; g < 4; g++) {
            unsigned r0, r1, r2, r3;
            unsigned addr = ldsm_addr(W_s, b_row0 + g * 16, cbase);
            asm volatile("ldmatrix.sync.aligned.m8n8.x4.shared.b16 {%0,%1,%2,%3}, [%4];"
                         : "=r"(r0), "=r"(r1), "=r"(r2), "=r"(r3) : "r"(addr));
            b[g * 2 + 0][0] = r0; b[g * 2 + 0][1] = r2;
            b[g * 2 + 1][0] = r1; b[g * 2 + 1][1] = r3;
        }
        #pragma unroll
        for (int mt = 0; mt < 2; mt++)
            #pragma unroll
            for (int nt = 0; nt < 8; nt++)
                asm volatile(
                    "mma.sync.aligned.m16n8k16.row.col.f32.f16.f16.f32 "
                    "{%0,%1,%2,%3}, {%4,%5,%6,%7}, {%8,%9}, {%0,%1,%2,%3};"
                    : "+f"(acc[mt][nt][0]), "+f"(acc[mt][nt][1]),
                      "+f"(acc[mt][nt][2]), "+f"(acc[mt][nt][3])
                    : "r"(a[mt][0]), "r"(a[mt][1]), "r"(a[mt][2]), "r"(a[mt][3]),
                      "r"(b[nt][0]), "r"(b[nt][1]));
    }

    // ---- epilogue: bias, LN stats, affine, relu ----
    const int gid  = lane >> 2;      // row-in-tile group 0..7
    const int pair = lane & 3;       // col pair

    // bias / gamma / beta for this lane's 16 columns
    float2 bv[8], gv[8], btv[8];
    #pragma unroll
    for (int nt = 0; nt < 8; nt++) {
        int col = n0 + nt * 8 + pair * 2;
        bv[nt]  = *(const float2*)(bn    + layer * HID + col);
        gv[nt]  = *(const float2*)(gamma + layer * HID + col);
        btv[nt] = *(const float2*)(beta  + layer * HID + col);
    }
    #pragma unroll
    for (int mt = 0; mt < 2; mt++)
        #pragma unroll
        for (int nt = 0; nt < 8; nt++) {
            acc[mt][nt][0] += bv[nt].x; acc[mt][nt][1] += bv[nt].y;
            acc[mt][nt][2] += bv[nt].x; acc[mt][nt][3] += bv[nt].y;
        }

    // per-lane partial sums: 4 rows (mt*2 + upper/lower)
    float s[4] = {0, 0, 0, 0}, qq[4] = {0, 0, 0, 0};
    #pragma unroll
    for (int mt = 0; mt < 2; mt++)
        #pragma unroll
        for (int nt = 0; nt < 8; nt++) {
            float c0 = acc[mt][nt][0], c1 = acc[mt][nt][1];
            float c2 = acc[mt][nt][2], c3 = acc[mt][nt][3];
            s [mt * 2 + 0] += c0 + c1;       qq[mt * 2 + 0] += c0 * c0 + c1 * c1;
            s [mt * 2 + 1] += c2 + c3;       qq[mt * 2 + 1] += c2 * c2 + c3 * c3;
        }
    #pragma unroll
    for (int v = 0; v < 4; v++) {
        s [v] += __shfl_xor_sync(0xffffffffu, s [v], 1);
        s [v] += __shfl_xor_sync(0xffffffffu, s [v], 2);
        qq[v] += __shfl_xor_sync(0xffffffffu, qq[v], 1);
        qq[v] += __shfl_xor_sync(0xffffffffu, qq[v], 2);
    }

    __syncthreads();   // done reading A_s/W_s; reuse as reduction buffers
    if (pair == 0) {
        #pragma unroll
        for (int v = 0; v < 4; v++) {
            int rl = m0 + (v >> 1) * 16 + (v & 1) * 8 + gid;   // row in tile
            red[wn * 128 + rl]       = s[v];
            red[256 + wn * 128 + rl] = qq[v];
        }
    }
    __syncthreads();

    const float inv128 = 1.0f / 128.0f;
    #pragma unroll
    for (int v = 0; v < 4; v++) {
        int rl  = m0 + (v >> 1) * 16 + (v & 1) * 8 + gid;
        int row = row0 + rl;
        float ts = red[rl] + red[128 + rl];
        float tq = red[256 + rl] + red[384 + rl];
        float mu  = ts * inv128;
        float var = tq * inv128 - mu * mu;
        float rs  = rsqrtf(var + LN_EPS);
        if (row < N_NODES) {
            int mt = v >> 1;
            int lo = (v & 1) * 2;   // acc index offset: 0 -> {0,1}, 1 -> {2,3}
            #pragma unroll
            for (int nt = 0; nt < 8; nt++) {
                float o0 = fmaxf((acc[mt][nt][lo + 0] - mu) * rs * gv[nt].x + btv[nt].x, 0.0f);
                float o1 = fmaxf((acc[mt][nt][lo + 1] - mu) * rs * gv[nt].y + btv[nt].y, 0.0f);
                int col = n0 + nt * 8 + pair * 2;
                if (write_fp32) {
                    *(float2*)(out_fp32 + (size_t)row * HID + col) = make_float2(o0, o1);
                } else {
                    __half2 h = __floats2half2_rn(o0, o1);
                    *(__half2*)(g_xh + (size_t)row * HID + col) = h;
                }
            }
        }
    }
}

// ---------------- graph pooling (batch sorted -> run-length partials) ---------
__global__ __launch_bounds__(128) void pool_kernel(
    const float* __restrict__ node_emb, const int* __restrict__ batch)
{
    __shared__ int sb[128];
    int n0 = blockIdx.x * 128;
    int c  = threadIdx.x;
    int nmax = min(128, N_NODES - n0);
    if (c < nmax) sb[c] = batch[n0 + c];
    __syncthreads();

    float sum = 0.f;
    int curg = sb[0];
    int runlen = 0;
    for (int t = 0; t < nmax; t++) {
        int g = sb[t];
        if (g != curg) {
            atomicAdd(&g_gsum[curg * HID + c], sum);
            if (c == 0) atomicAdd(&g_gcnt[curg], (float)runlen);
            sum = 0.f; runlen = 0; curg = g;
        }
        sum += node_emb[(size_t)(n0 + t) * HID + c];
        runlen++;
    }
    atomicAdd(&g_gsum[curg * HID + c], sum);
    if (c == 0) atomicAdd(&g_gcnt[curg], (float)runlen);
}

__global__ void finalize_kernel(float* __restrict__ out_graph) {
    int g = blockIdx.x;
    int c = threadIdx.x;
    float cnt = fmaxf(g_gcnt[g], 1.0f);
    out_graph[g * HID + c] = g_gsum[g * HID + c] / cnt;
}

extern "C" void kernel_launch(void* const* d_in, const int* in_sizes, int n_in,
                              void* d_out, int out_size)
{
    const float* x     = (const float*)d_in[0];
    const float* Wn    = (const float*)d_in[1];
    const float* bn    = (const float*)d_in[2];
    const float* Wr    = (const float*)d_in[3];
    const float* gamma = (const float*)d_in[4];
    const float* beta  = (const float*)d_in[5];
    const int*   ei    = (const int*)  d_in[6];
    const int*   batch = (const int*)  d_in[7];
    float* out = (float*)d_out;
    float* out_graph = out;                       // [64,128]
    float* out_node  = out + N_GRAPHS * HID;      // [50000,128]

    const int nE = in_sizes[6] / 2;

    static bool inited = false;
    if (!inited) {
        inited = true;
        cudaFuncSetAttribute(hmma_ln_kernel,
                             cudaFuncAttributeMaxDynamicSharedMemorySize,
                             2 * GT_ROWS * KTOT * (int)sizeof(__half));
    }
    const size_t smem = 2 * GT_ROWS * KTOT * sizeof(__half);   // 128 KB

    // CSR build
    zero_small_kernel<<<(N_NODES + 255) / 256, 256>>>();
    count_kernel<<<(nE + 255) / 256, 256>>>(ei, nE);
    scan1_kernel<<<SCAN_B, 256>>>();
    scan2_kernel<<<1, 256>>>();
    scan3_kernel<<<SCAN_B, 256>>>(nE);
    fill_kernel<<<(nE + 255) / 256, 256>>>(ei, nE);

    // fp16 input shadow + transposed fp16 weights
    convert_half_kernel<<<((N_NODES * HID / 4) + 255) / 256, 256>>>(x);
    wtrans_kernel<<<(N_LAYERS * HID * KTOT + 255) / 256, 256>>>(Wn, Wr);

    const int gemm_grid   = (N_NODES + GT_ROWS - 1) / GT_ROWS;
    const int gather_grid = (N_NODES * 32 + 255) / 256;

    for (int l = 0; l < N_LAYERS; l++) {
        gather_kernel<<<gather_grid, 256>>>();
        hmma_ln_kernel<<<gemm_grid, 256, smem>>>(
            bn, gamma, beta, out_node, l, (l == N_LAYERS - 1) ? 1 : 0);
    }

    pool_kernel<<<(N_NODES + 127) / 128, 128>>>(out_node, batch);
    finalize_kernel<<<N_GRAPHS, HID>>>(out_graph);
}